// round 11
// baseline (speedup 1.0000x reference)
#include <cuda_runtime.h>
#include <math.h>

#define CCH 128
#define HW  262144          // 512*512
#define NT  1024
#define NBIN 4096           // 12-bit prefix bins

// static scratch (allocation-free)
__device__ unsigned int g_hist[(size_t)CCH * NBIN];   // 2MB, L2-resident
__device__ unsigned int g_cand[(size_t)CCH * HW];     // candidate keys
__device__ double g_partial[CCH];

__device__ __forceinline__ unsigned int fkey(float x) {
    unsigned int u = __float_as_uint(x);
    return (u & 0x80000000u) ? ~u : (u | 0x80000000u);
}
__device__ __forceinline__ float dkey(unsigned int k) {
    return __uint_as_float((k & 0x80000000u) ? (k & 0x7fffffffu) : ~k);
}
// reference binning: b = clip(int32((v-mn)/dd * 255), 0, 255); monotone in key
__device__ __forceinline__ int binf(unsigned int k, float mn, float dd) {
    float v = dkey(k);
    float u = (v - mn) / dd;
    int b = (int)(u * 255.0f);
    return b < 0 ? 0 : (b > 255 ? 255 : b);
}

__global__ void zero_kernel() {
    size_t i = (size_t)blockIdx.x * blockDim.x + threadIdx.x;   // 128*1024 = 131072
    ((uint4*)g_hist)[i] = make_uint4(0u, 0u, 0u, 0u);           // 131072*16B = 2MB
}

__global__ void finish_kernel(float* out) {
    double s = 0.0;
    for (int c = 0; c < CCH; c++) s += g_partial[c];
    out[0] = (float)(s * (0.01 / ((double)CCH * (double)HW)));
}

// smem layout (u32 words)
#define SMEM_WORDS 18840
#define SMEM_BYTES (SMEM_WORDS * 4)

__global__ void __launch_bounds__(1024, 1)
main_kernel(const float* __restrict__ input, const float* __restrict__ mask,
            const float* __restrict__ thist, const float* __restrict__ tmin_,
            const float* __restrict__ tmax_, float* __restrict__ out)
{
    extern __shared__ unsigned int smem[];
    unsigned int* HIST   = smem;              // 4096 u32 counts (12-bit bins)
    unsigned int* TT     = smem + 4096;       // 2048: 4096 u16 classify table
    unsigned int* WH     = TT + 2048;         // 8192: 32 warps x 256 select hists (+cdf temp)
    unsigned int* cutBin = WH + 8192;         // 256
    unsigned int* cutR   = cutBin + 256;      // 256
    unsigned int* cutSlot= cutR + 256;        // 256
    unsigned int* thA    = cutSlot + 256;     // 256 threshold keys (sorted; 0-sentinels)
    unsigned int* kbA    = thA + 256;         // 256 boundary keys (0 = sentinel)
    unsigned int* bSlot  = kbA + 256;         // 256
    unsigned int* bPre   = bSlot + 256;       // 256
    unsigned int* rankA  = bPre + 256;        // 257
    unsigned int* uniqB  = rankA + 257;       // 512 active bins (sorted)
    unsigned int* segOff = uniqB + 512;       // 512
    unsigned int* segLen = segOff + 512;      // 512
    unsigned int* cursor = segLen + 512;      // 512
    unsigned int* sgrp   = cursor + 512;      // 65 (64 groups + total)
    unsigned int* Karr   = sgrp + 65;         // 256
    unsigned int* red    = Karr + 256;        // 80

    const int c   = blockIdx.x;
    const int tid = threadIdx.x;
    const int lane = tid & 31;
    const int wz   = tid >> 5;
    const float4* in4 = (const float4*)(input + (size_t)c * HW);
    const float4* mk4 = (const float4*)mask;
    unsigned int* candC = g_cand + (size_t)c * HW;
    unsigned int* histC = g_hist + (size_t)c * NBIN;

    // ---------- Pass 1: min/max + 12-bit histogram via global REDG (L2-resident) ----------
    {
        unsigned kmin = 0xffffffffu, kmax = 0u;
        for (int i = tid; i < HW / 4; i += NT) {
            float4 a = in4[i], m = mk4[i];
            unsigned k0 = fkey(a.x * m.x), k1 = fkey(a.y * m.y);
            unsigned k2 = fkey(a.z * m.z), k3 = fkey(a.w * m.w);
            kmin = min(kmin, min(min(k0, k1), min(k2, k3)));
            kmax = max(kmax, max(max(k0, k1), max(k2, k3)));
            atomicAdd(&histC[k0 >> 20], 1u);   // no return used -> RED
            atomicAdd(&histC[k1 >> 20], 1u);
            atomicAdd(&histC[k2 >> 20], 1u);
            atomicAdd(&histC[k3 >> 20], 1u);
        }
        #pragma unroll
        for (int o = 16; o; o >>= 1) {
            kmin = min(kmin, __shfl_down_sync(0xffffffffu, kmin, o));
            kmax = max(kmax, __shfl_down_sync(0xffffffffu, kmax, o));
        }
        if (lane == 0) { red[wz] = kmin; red[32 + wz] = kmax; }
    }
    __threadfence();      // make this CTA's REDs visible before readback
    __syncthreads();

    // ---------- readback histogram (16KB) + min/max finalize ----------
    for (int i = tid; i < NBIN; i += NT) HIST[i] = histC[i];
    if (tid == 0) {
        unsigned mn = red[0], mx = red[32];
        for (int w = 1; w < 32; w++) { mn = min(mn, red[w]); mx = max(mx, red[32 + w]); }
        red[64] = mn; red[65] = mx;
    }
    __syncthreads();

    // ---------- group sums (64 groups of 64) + CDF->K ----------
    if (tid >= 64 && tid < 128) {
        int g = tid - 64;
        unsigned s = 0;
        for (int w = 0; w < 64; w++) s += HIST[g * 64 + w];
        sgrp[g] = s;
    } else if (tid == 32) {
        float* cdf = (float*)WH;
        float s = 0.0f;
        for (int j = 0; j < 256; j++) { s += thist[c * 256 + j]; cdf[j] = s; }
        float tot = s;
        for (int j = 0; j < 256; j++) {
            float t = (cdf[j] / tot) * 262144.0f;
            float f = floorf(t);
            if (f < 0.0f) f = 0.0f;
            if (f > 262144.0f) f = 262144.0f;
            Karr[j] = (unsigned)f;
        }
    }
    __syncthreads();
    if (tid == 0) {
        unsigned acc = 0;
        for (int g = 0; g < 64; g++) { unsigned t = sgrp[g]; sgrp[g] = acc; acc += t; }
        sgrp[64] = acc;
    }
    __syncthreads();

    // ---------- cut bin location + boundary key search ----------
    if (tid < 256) {
        unsigned k = Karr[tid];
        if (k == 0) { cutBin[tid] = 0xffffffffu; cutR[tid] = 0; }
        else {
            int lo = 0, hi = 63;
            while (lo < hi) { int mid = (lo + hi + 1) >> 1; if (sgrp[mid] < k) lo = mid; else hi = mid - 1; }
            unsigned acc = sgrp[lo];
            int bin = lo * 64;
            for (;; bin++) {
                unsigned cnt = HIST[bin];
                if (acc + cnt >= k) break;
                acc += cnt;
            }
            cutBin[tid] = (unsigned)bin;
            cutR[tid] = k - acc;
        }
    } else if (tid < 511) {
        int j = tid - 255;          // 1..255
        unsigned mnk = red[64], mxk = red[65];
        float mn = dkey(mnk), mx = dkey(mxk);
        float dd = fmaxf(mx - mn, 1e-8f);
        if (binf(mxk, mn, dd) < j) kbA[j] = 0u;
        else {
            unsigned lo = mnk, hi = mxk;
            while (lo < hi) {
                unsigned mid = lo + ((hi - lo) >> 1);
                if (binf(mid, mn, dd) >= j) hi = mid; else lo = mid + 1;
            }
            kbA[j] = lo;
        }
    }
    __syncthreads();

    // ---------- boundary prefix counts + merge active bins ----------
    if (tid >= 256 && tid < 511) {
        int j = tid - 255;
        unsigned kb = kbA[j];
        if (kb != 0u) {
            unsigned p = kb >> 20, g = p >> 6;
            unsigned s = sgrp[g];
            for (unsigned b = g << 6; b < p; b++) s += HIST[b];
            bPre[j] = s;
        }
    } else if (tid == 512) {       // merge sorted cut bins + boundary prefixes (dedup)
        int i = 0, j = 1, n = 0;
        unsigned off = 0;
        for (;;) {
            unsigned a = 0xffffffffu, b = 0xffffffffu;
            while (i < 256 && cutBin[i] == 0xffffffffu) i++;
            if (i < 256) a = cutBin[i];
            while (j < 256 && kbA[j] == 0u) j++;
            if (j < 256) b = kbA[j] >> 20;
            if (a == 0xffffffffu && b == 0xffffffffu) break;
            unsigned v = min(a, b);
            while (i < 256 && cutBin[i] == v) i++;
            while (j < 256 && kbA[j] != 0u && (kbA[j] >> 20) == v) j++;
            unsigned cnt = HIST[v];
            uniqB[n] = v; segOff[n] = off; segLen[n] = cnt;
            off += cnt; n++;
        }
        red[66] = (unsigned)n;
        red[67] = off;            // total candidates
    }
    __syncthreads();
    const int nU = (int)red[66];

    // ---------- slots + defaults (cutLow lives in cutSlot temporarily? keep separate) ----------
    if (tid < 256) {
        thA[tid] = 0u;
        if (cutBin[tid] != 0xffffffffu) {
            unsigned p = cutBin[tid];
            int lo = 0, hi = nU - 1;
            while (lo < hi) { int mid = (lo + hi) >> 1; if (uniqB[mid] < p) lo = mid + 1; else hi = mid; }
            cutSlot[tid] = (unsigned)lo;
        }
    } else if (tid < 511) {
        int j = tid - 255;
        if (kbA[j] != 0u) {
            unsigned p = kbA[j] >> 20;
            int lo = 0, hi = nU - 1;
            while (lo < hi) { int mid = (lo + hi) >> 1; if (uniqB[mid] < p) lo = mid + 1; else hi = mid; }
            bSlot[j] = (unsigned)lo;
        }
    }
    if (tid < 257) rankA[tid] = (tid == 0) ? 0u : (unsigned)HW;
    if (tid < 512) cursor[tid] = 0;
    __syncthreads();

    // ---------- build T12 table (4096 u16) over TT ----------
    {
        // cutLow[j] = 0 for K=0 else cutBin[j]; sorted nondecreasing. Reuse HIST? No: read cutBin/Karr.
        int p0 = tid * 4;
        // idx = #{cutLow < p0}
        int lo = 0, hi = 256;
        while (lo < hi) {
            int mid = (lo + hi) >> 1;
            unsigned cl = (Karr[mid] == 0) ? 0u : cutBin[mid];
            if ((int)cl < p0) lo = mid + 1; else hi = mid;
        }
        int idx = lo;
        #pragma unroll
        for (int w = 0; w < 2; w++) {
            unsigned word = 0;
            #pragma unroll
            for (int e = 0; e < 2; e++) {
                int p = p0 + w * 2 + e;
                for (;;) {
                    if (idx >= 256) break;
                    unsigned cl = (Karr[idx] == 0) ? 0u : cutBin[idx];
                    if ((int)cl < p) idx++; else break;
                }
                word |= ((unsigned)min(idx, 255)) << (16 * e);
            }
            TT[tid * 2 + w] = word;
        }
    }
    __syncthreads();
    if (tid < nU) ((unsigned short*)TT)[uniqB[tid]] = (unsigned short)(0x8000u | (unsigned)tid);
    __syncthreads();

    // ---------- Pass 2 (fused): classify -> compact candidates OR accumulate loss ----------
    const float tmn = tmin_[c];
    const float scl = tmax_[c] - tmn;
    float acc = 0.0f;
    {
        const unsigned short* T12 = (const unsigned short*)TT;
        for (int i = tid; i < HW / 4; i += NT) {
            float4 a = in4[i], m = mk4[i];
            float vv[4] = {a.x * m.x, a.y * m.y, a.z * m.z, a.w * m.w};
            #pragma unroll
            for (int e = 0; e < 4; e++) {
                float v = vv[e];
                unsigned key = fkey(v);
                unsigned t = T12[key >> 20];
                if (t & 0x8000u) {
                    unsigned s = t & 0x7fffu;
                    candC[segOff[s] + atomicAdd(&cursor[s], 1u)] = key;
                } else {
                    float bf = (float)t * (1.0f / 255.0f);
                    float df = v - fmaf(bf, scl, tmn);
                    acc = fmaf(df, df, acc);
                }
            }
        }
    }
    __syncthreads();

    // ---------- Phase D: resolve thresholds (3 rounds over 20 suffix bits) + boundary ranks ----------
    {
        unsigned* wh = WH + wz * 256;
        for (int q = wz; q < 511; q += 32) {
            if (q < 256) {
                if (cutBin[q] == 0xffffffffu) continue;
                unsigned slot = cutSlot[q];
                unsigned off = segOff[slot], len = segLen[slot], r = cutR[q];
                unsigned known = cutBin[q];
                #pragma unroll
                for (int t = 0; t < 3; t++) {
                    const int s  = (t == 0) ? 12 : (t == 1) ? 4 : 0;
                    const int w  = (t == 2) ? 4 : 8;
                    const unsigned nb = 1u << w;
                    for (unsigned i = lane; i < nb; i += 32) wh[i] = 0;
                    __syncwarp();
                    for (unsigned i = lane; i < len; i += 32) {
                        unsigned key = candC[off + i];
                        if ((key >> (s + w)) == known)
                            atomicAdd(&wh[(key >> s) & (nb - 1u)], 1u);
                    }
                    __syncwarp();
                    unsigned sel = 0, rem = 0;
                    if (lane == 0) {
                        unsigned a2 = 0; unsigned b = 0;
                        for (;; b++) { unsigned ct = wh[b]; if (a2 + ct >= r) break; a2 += ct; }
                        sel = b; rem = r - a2;
                    }
                    sel = __shfl_sync(0xffffffffu, sel, 0);
                    rem = __shfl_sync(0xffffffffu, rem, 0);
                    known = (known << w) | sel;
                    r = rem;
                    __syncwarp();
                }
                if (lane == 0) thA[q] = known;
            } else {
                int j = q - 255;
                if (kbA[j] == 0u) continue;
                unsigned slot = bSlot[j];
                unsigned off = segOff[slot], len = segLen[slot];
                unsigned bs = kbA[j] & 0xfffffu;
                unsigned cnt = 0;
                for (unsigned i = lane; i < len; i += 32)
                    cnt += ((candC[off + i] & 0xfffffu) < bs) ? 1u : 0u;
                #pragma unroll
                for (int o = 16; o; o >>= 1) cnt += __shfl_down_sync(0xffffffffu, cnt, o);
                if (lane == 0) rankA[j] = bPre[j] + cnt;
            }
        }
    }
    __syncthreads();

    // ---------- Epilogue: loss for candidates (thA binary search) ----------
    {
        const int totalCand = (int)red[67];
        for (int i = tid; i < totalCand; i += NT) {
            unsigned key = candC[i];
            int lo = 0, hi = 256;
            while (lo < hi) { int mid = (lo + hi) >> 1; if (thA[mid] < key) lo = mid + 1; else hi = mid; }
            int bm = min(lo, 255);
            float v = dkey(key);
            float bf = (float)bm * (1.0f / 255.0f);
            float df = v - fmaf(bf, scl, tmn);
            acc = fmaf(df, df, acc);
        }
    }

    // ---------- outputs ----------
    if (tid < 256) out[1 + c * 256 + tid] = (float)(rankA[tid + 1] - rankA[tid]);

    #pragma unroll
    for (int o = 16; o; o >>= 1) acc += __shfl_down_sync(0xffffffffu, acc, o);
    float* fred = (float*)uniqB;    // free now
    if (lane == 0) fred[wz] = acc;
    __syncthreads();
    if (tid == 0) {
        float s = 0.0f;
        for (int w = 0; w < 32; w++) s += fred[w];
        g_partial[c] = (double)s;
        out[1 + 32768 + c]       = dkey(red[64]);
        out[1 + 32768 + 128 + c] = dkey(red[65]);
    }
}

extern "C" void kernel_launch(void* const* d_in, const int* in_sizes, int n_in,
                              void* d_out, int out_size)
{
    const float* input = (const float*)d_in[0];
    const float* mask  = (const float*)d_in[1];
    const float* thist = (const float*)d_in[2];
    const float* tmn   = (const float*)d_in[3];
    const float* tmx   = (const float*)d_in[4];
    float* out = (float*)d_out;

    cudaFuncSetAttribute(main_kernel, cudaFuncAttributeMaxDynamicSharedMemorySize, SMEM_BYTES);

    zero_kernel<<<128, 1024>>>();
    main_kernel<<<CCH, 1024, SMEM_BYTES>>>(input, mask, thist, tmn, tmx, out);
    finish_kernel<<<1, 1>>>(out);
}

// round 12
// speedup vs baseline: 2.2508x; 2.2508x over previous
#include <cuda_runtime.h>
#include <math.h>

#define CCH 128
#define HW  262144          // 512*512
#define NT  1024

// static scratch (allocation-free)
__device__ unsigned int g_cand[(size_t)CCH * HW];     // candidate keys
__device__ double g_partial[CCH];
__device__ unsigned int g_arrive = 0;

__device__ __forceinline__ unsigned int fkey(float x) {
    unsigned int u = __float_as_uint(x);
    return (u & 0x80000000u) ? ~u : (u | 0x80000000u);
}
__device__ __forceinline__ float dkey(unsigned int k) {
    return __uint_as_float((k & 0x80000000u) ? (k & 0x7fffffffu) : ~k);
}
// reference binning: b = clip(int32((v-mn)/dd * 255), 0, 255); monotone in key
__device__ __forceinline__ int binf(unsigned int k, float mn, float dd) {
    float v = dkey(k);
    float u = (v - mn) / dd;
    int b = (int)(u * 255.0f);
    return b < 0 ? 0 : (b > 255 ? 255 : b);
}

// smem layout (u32 words)
#define SMEM_WORDS 45906
#define SMEM_BYTES (SMEM_WORDS * 4)

__global__ void __launch_bounds__(1024, 1)
main_kernel(const float* __restrict__ input, const float* __restrict__ mask,
            const float* __restrict__ thist, const float* __restrict__ tmin_,
            const float* __restrict__ tmax_, float* __restrict__ out)
{
    extern __shared__ unsigned int smem[];
    unsigned int* HIST   = smem;              // 32768: u16x2 hist -> T16 table
    unsigned int* WH     = smem + 32768;      // 8192: warp select hists (also cdf temp)
    unsigned int* cutBin = WH + 8192;         // 256
    unsigned int* cutR   = cutBin + 256;      // 256
    unsigned int* cutSlot= cutR + 256;        // 256
    unsigned int* thA    = cutSlot + 256;     // 256 threshold keys (sorted, 0-sentinels)
    unsigned int* kbA    = thA + 256;         // 256 boundary keys (0 = sentinel)
    unsigned int* bSlot  = kbA + 256;         // 256
    unsigned int* bPre   = bSlot + 256;       // 256
    unsigned int* rankA  = bPre + 256;        // 257
    unsigned int* uniqB  = rankA + 257;       // 512 active bins (sorted)
    unsigned int* segOff = uniqB + 512;       // 512
    unsigned int* segLen = segOff + 512;      // 512
    unsigned int* cursor = segLen + 512;      // 512
    unsigned int* sgrp   = cursor + 512;      // 257
    unsigned int* cutLow = sgrp + 257;        // 256 (cut prefixes, K=0 -> 0)
    unsigned int* Karr   = cutLow + 256;      // 256
    unsigned int* red    = Karr + 256;        // 80

    const int c   = blockIdx.x;
    const int tid = threadIdx.x;
    const int lane = tid & 31;
    const int wz   = tid >> 5;
    const float4* in4 = (const float4*)(input + (size_t)c * HW);
    const float4* mk4 = (const float4*)mask;
    unsigned int* candC = g_cand + (size_t)c * HW;

    for (int i = tid; i < 32768; i += NT) HIST[i] = 0;
    __syncthreads();

    // ---------- Pass 1: min/max + 16-bit-prefix histogram (packed u16 smem atomics) ----------
    {
        unsigned kmin = 0xffffffffu, kmax = 0u;
        #pragma unroll 1
        for (int i = tid; i < HW / 4; i += 2 * NT) {
            float4 a0 = in4[i], a1 = in4[i + NT];
            float4 m0 = mk4[i], m1 = mk4[i + NT];
            unsigned k0 = fkey(a0.x * m0.x), k1 = fkey(a0.y * m0.y);
            unsigned k2 = fkey(a0.z * m0.z), k3 = fkey(a0.w * m0.w);
            unsigned k4 = fkey(a1.x * m1.x), k5 = fkey(a1.y * m1.y);
            unsigned k6 = fkey(a1.z * m1.z), k7 = fkey(a1.w * m1.w);
            kmin = min(kmin, min(min(min(k0, k1), min(k2, k3)), min(min(k4, k5), min(k6, k7))));
            kmax = max(kmax, max(max(max(k0, k1), max(k2, k3)), max(max(k4, k5), max(k6, k7))));
            atomicAdd(&HIST[k0 >> 17], 1u << ((k0 >> 12) & 16));
            atomicAdd(&HIST[k1 >> 17], 1u << ((k1 >> 12) & 16));
            atomicAdd(&HIST[k2 >> 17], 1u << ((k2 >> 12) & 16));
            atomicAdd(&HIST[k3 >> 17], 1u << ((k3 >> 12) & 16));
            atomicAdd(&HIST[k4 >> 17], 1u << ((k4 >> 12) & 16));
            atomicAdd(&HIST[k5 >> 17], 1u << ((k5 >> 12) & 16));
            atomicAdd(&HIST[k6 >> 17], 1u << ((k6 >> 12) & 16));
            atomicAdd(&HIST[k7 >> 17], 1u << ((k7 >> 12) & 16));
        }
        #pragma unroll
        for (int o = 16; o; o >>= 1) {
            kmin = min(kmin, __shfl_down_sync(0xffffffffu, kmin, o));
            kmax = max(kmax, __shfl_down_sync(0xffffffffu, kmax, o));
        }
        if (lane == 0) { red[wz] = kmin; red[32 + wz] = kmax; }
    }
    __syncthreads();
    if (tid == 0) {
        unsigned mn = red[0], mx = red[32];
        for (int w = 1; w < 32; w++) { mn = min(mn, red[w]); mx = max(mx, red[32 + w]); }
        red[64] = mn; red[65] = mx;
    }

    // ---------- group sums + CDF->K ----------
    if (tid >= 64 && tid < 320) {
        int g = tid - 64;
        unsigned s = 0;
        for (int w = 0; w < 128; w++) {
            unsigned v = HIST[g * 128 + w];
            s += (v & 0xffffu) + (v >> 16);
        }
        sgrp[g] = s;
    } else if (tid == 32) {
        float* cdf = (float*)WH;
        float s = 0.0f;
        for (int j = 0; j < 256; j++) { s += thist[c * 256 + j]; cdf[j] = s; }
        float tot = s;
        for (int j = 0; j < 256; j++) {
            float t = (cdf[j] / tot) * 262144.0f;
            float f = floorf(t);
            if (f < 0.0f) f = 0.0f;
            if (f > 262144.0f) f = 262144.0f;
            Karr[j] = (unsigned)f;
        }
    }
    __syncthreads();
    if (tid == 0) {
        unsigned acc = 0;
        for (int g = 0; g < 256; g++) { unsigned t = sgrp[g]; sgrp[g] = acc; acc += t; }
        sgrp[256] = acc;
    }
    __syncthreads();

    // ---------- cut bin location + boundary key search ----------
    if (tid < 256) {
        unsigned k = Karr[tid];
        if (k == 0) { cutBin[tid] = 0xffffffffu; cutR[tid] = 0; }
        else {
            int lo = 0, hi = 255;
            while (lo < hi) { int mid = (lo + hi + 1) >> 1; if (sgrp[mid] < k) lo = mid; else hi = mid - 1; }
            unsigned acc = sgrp[lo];
            int bin = lo * 256;
            for (;; bin++) {
                unsigned w = HIST[bin >> 1];
                unsigned cnt = (bin & 1) ? (w >> 16) : (w & 0xffffu);
                if (acc + cnt >= k) break;
                acc += cnt;
            }
            cutBin[tid] = (unsigned)bin;
            cutR[tid] = k - acc;
        }
    } else if (tid < 511) {
        int j = tid - 255;          // 1..255
        unsigned mnk = red[64], mxk = red[65];
        float mn = dkey(mnk), mx = dkey(mxk);
        float dd = fmaxf(mx - mn, 1e-8f);
        if (binf(mxk, mn, dd) < j) kbA[j] = 0u;
        else {
            unsigned lo = mnk, hi = mxk;
            while (lo < hi) {
                unsigned mid = lo + ((hi - lo) >> 1);
                if (binf(mid, mn, dd) >= j) hi = mid; else lo = mid + 1;
            }
            kbA[j] = lo;
        }
    }
    __syncthreads();

    // ---------- boundary prefix counts + cutLow + merge active bins ----------
    if (tid < 256) {
        cutLow[tid] = (Karr[tid] == 0) ? 0u : cutBin[tid];
    } else if (tid < 511) {
        int j = tid - 255;
        unsigned kb = kbA[j];
        if (kb != 0u) {
            unsigned p = kb >> 16, g = p >> 8;
            unsigned s = sgrp[g];
            for (unsigned b = g << 8; b < p; b++) {
                unsigned w = HIST[b >> 1];
                s += (b & 1) ? (w >> 16) : (w & 0xffffu);
            }
            bPre[j] = s;
        }
    } else if (tid == 512) {       // merge sorted cut bins + boundary prefixes (dedup)
        int i = 0, j = 1, n = 0;
        unsigned off = 0;
        for (;;) {
            unsigned a = 0xffffffffu, b = 0xffffffffu;
            while (i < 256 && cutBin[i] == 0xffffffffu) i++;
            if (i < 256) a = cutBin[i];
            while (j < 256 && kbA[j] == 0u) j++;
            if (j < 256) b = kbA[j] >> 16;
            if (a == 0xffffffffu && b == 0xffffffffu) break;
            unsigned v = min(a, b);
            while (i < 256 && cutBin[i] == v) i++;
            while (j < 256 && kbA[j] != 0u && (kbA[j] >> 16) == v) j++;
            unsigned w = HIST[v >> 1];
            unsigned cnt = (v & 1) ? (w >> 16) : (w & 0xffffu);
            uniqB[n] = v; segOff[n] = off; segLen[n] = cnt;
            off += cnt; n++;
        }
        red[66] = (unsigned)n;
        red[67] = off;            // total candidates
    }
    __syncthreads();
    const int nU = (int)red[66];

    // ---------- slots + defaults ----------
    if (tid < 256) {
        thA[tid] = 0u;
        if (cutBin[tid] != 0xffffffffu) {
            unsigned p = cutBin[tid];
            int lo = 0, hi = nU - 1;
            while (lo < hi) { int mid = (lo + hi) >> 1; if (uniqB[mid] < p) lo = mid + 1; else hi = mid; }
            cutSlot[tid] = (unsigned)lo;
        }
    } else if (tid < 511) {
        int j = tid - 255;
        if (kbA[j] != 0u) {
            unsigned p = kbA[j] >> 16;
            int lo = 0, hi = nU - 1;
            while (lo < hi) { int mid = (lo + hi) >> 1; if (uniqB[mid] < p) lo = mid + 1; else hi = mid; }
            bSlot[j] = (unsigned)lo;
        }
    }
    if (tid < 257) rankA[tid] = (tid == 0) ? 0u : (unsigned)HW;
    if (tid < 512) cursor[tid] = 0;
    __syncthreads();

    // ---------- build T16 table over HIST: bm for inactive prefixes, slot for active ----------
    {
        int p0 = tid * 64;
        int lo = 0, hi = 256;
        while (lo < hi) { int mid = (lo + hi) >> 1; if ((int)cutLow[mid] < p0) lo = mid + 1; else hi = mid; }
        int idx = lo;
        #pragma unroll 4
        for (int w = 0; w < 32; w++) {
            unsigned word = 0;
            #pragma unroll
            for (int e = 0; e < 2; e++) {
                int p = p0 + w * 2 + e;
                while (idx < 256 && (int)cutLow[idx] < p) idx++;
                word |= ((unsigned)min(idx, 255)) << (16 * e);
            }
            HIST[(p0 >> 1) + w] = word;
        }
    }
    __syncthreads();
    if (tid < nU) ((unsigned short*)HIST)[uniqB[tid]] = (unsigned short)(0x8000u | (unsigned)tid);
    __syncthreads();

    // ---------- Pass 2 (fused): classify -> compact candidates OR accumulate loss ----------
    const float tmn = tmin_[c];
    const float scl = tmax_[c] - tmn;
    float acc = 0.0f;
    {
        const unsigned short* T16 = (const unsigned short*)HIST;
        #pragma unroll 1
        for (int i = tid; i < HW / 4; i += 2 * NT) {
            float4 a0 = in4[i], a1 = in4[i + NT];
            float4 m0 = mk4[i], m1 = mk4[i + NT];
            float vv[8] = {a0.x * m0.x, a0.y * m0.y, a0.z * m0.z, a0.w * m0.w,
                           a1.x * m1.x, a1.y * m1.y, a1.z * m1.z, a1.w * m1.w};
            #pragma unroll
            for (int e = 0; e < 8; e++) {
                float v = vv[e];
                unsigned key = fkey(v);
                unsigned t = T16[key >> 16];
                if (t & 0x8000u) {
                    unsigned s = t & 0x7fffu;
                    candC[segOff[s] + atomicAdd(&cursor[s], 1u)] = key;
                } else {
                    float bf = (float)t * (1.0f / 255.0f);
                    float df = v - fmaf(bf, scl, tmn);
                    acc = fmaf(df, df, acc);
                }
            }
        }
    }
    __syncthreads();

    // ---------- Phase D: resolve thresholds + boundary ranks on candidates ----------
    {
        unsigned* wh = WH + wz * 256;
        for (int q = wz; q < 511; q += 32) {
            if (q < 256) {
                if (cutBin[q] == 0xffffffffu) continue;
                unsigned slot = cutSlot[q];
                unsigned off = segOff[slot], len = segLen[slot], r = cutR[q];
                // round A: high byte of 16-bit suffix
                for (int i = lane; i < 256; i += 32) wh[i] = 0;
                __syncwarp();
                for (unsigned i = lane; i < len; i += 32)
                    atomicAdd(&wh[(candC[off + i] >> 8) & 0xffu], 1u);
                __syncwarp();
                unsigned hi8 = 0, rem = 0;
                if (lane == 0) {
                    unsigned a2 = 0; int b = 0;
                    for (;; b++) { unsigned ct = wh[b]; if (a2 + ct >= r) break; a2 += ct; }
                    hi8 = (unsigned)b; rem = r - a2;
                }
                hi8 = __shfl_sync(0xffffffffu, hi8, 0);
                rem = __shfl_sync(0xffffffffu, rem, 0);
                // round B: low byte
                for (int i = lane; i < 256; i += 32) wh[i] = 0;
                __syncwarp();
                for (unsigned i = lane; i < len; i += 32) {
                    unsigned sfx = candC[off + i] & 0xffffu;
                    if ((sfx >> 8) == hi8) atomicAdd(&wh[sfx & 0xffu], 1u);
                }
                __syncwarp();
                if (lane == 0) {
                    unsigned a2 = 0; int b = 0;
                    for (;; b++) { unsigned ct = wh[b]; if (a2 + ct >= rem) break; a2 += ct; }
                    thA[q] = (cutBin[q] << 16) | (hi8 << 8) | (unsigned)b;
                }
                __syncwarp();
            } else {
                int j = q - 255;
                if (kbA[j] == 0u) continue;
                unsigned slot = bSlot[j];
                unsigned off = segOff[slot], len = segLen[slot];
                unsigned bs = kbA[j] & 0xffffu;
                unsigned cnt = 0;
                for (unsigned i = lane; i < len; i += 32)
                    cnt += ((candC[off + i] & 0xffffu) < bs) ? 1u : 0u;
                #pragma unroll
                for (int o = 16; o; o >>= 1) cnt += __shfl_down_sync(0xffffffffu, cnt, o);
                if (lane == 0) rankA[j] = bPre[j] + cnt;
            }
        }
    }
    __syncthreads();

    // ---------- Epilogue: loss for candidates (thA binary search) ----------
    {
        const int totalCand = (int)red[67];
        for (int i = tid; i < totalCand; i += NT) {
            unsigned key = candC[i];
            int lo = 0, hi = 256;
            while (lo < hi) { int mid = (lo + hi) >> 1; if (thA[mid] < key) lo = mid + 1; else hi = mid; }
            int bm = min(lo, 255);
            float v = dkey(key);
            float bf = (float)bm * (1.0f / 255.0f);
            float df = v - fmaf(bf, scl, tmn);
            acc = fmaf(df, df, acc);
        }
    }

    // ---------- outputs ----------
    if (tid < 256) out[1 + c * 256 + tid] = (float)(rankA[tid + 1] - rankA[tid]);

    #pragma unroll
    for (int o = 16; o; o >>= 1) acc += __shfl_down_sync(0xffffffffu, acc, o);
    float* fred = (float*)uniqB;    // free now
    if (lane == 0) fred[wz] = acc;
    __syncthreads();
    if (tid == 0) {
        float s = 0.0f;
        for (int w = 0; w < 32; w++) s += fred[w];
        g_partial[c] = (double)s;
        out[1 + 32768 + c]       = dkey(red[64]);
        out[1 + 32768 + 128 + c] = dkey(red[65]);

        // last CTA finalizes the scalar loss (single-kernel pipeline)
        __threadfence();
        unsigned t = atomicAdd(&g_arrive, 1u);
        if (t == CCH - 1) {
            __threadfence();
            double s2 = 0.0;
            for (int i = 0; i < CCH; i++) s2 += g_partial[i];
            out[0] = (float)(s2 * (0.01 / ((double)CCH * (double)HW)));
            g_arrive = 0;     // reset for next graph replay
            __threadfence();
        }
    }
}

extern "C" void kernel_launch(void* const* d_in, const int* in_sizes, int n_in,
                              void* d_out, int out_size)
{
    const float* input = (const float*)d_in[0];
    const float* mask  = (const float*)d_in[1];
    const float* thist = (const float*)d_in[2];
    const float* tmn   = (const float*)d_in[3];
    const float* tmx   = (const float*)d_in[4];
    float* out = (float*)d_out;

    cudaFuncSetAttribute(main_kernel, cudaFuncAttributeMaxDynamicSharedMemorySize, SMEM_BYTES);
    main_kernel<<<CCH, 1024, SMEM_BYTES>>>(input, mask, thist, tmn, tmx, out);
}